// round 2
// baseline (speedup 1.0000x reference)
#include <cuda_runtime.h>

#define BB 4
#define FF 32
#define CC 4096
#define TT 32
#define EE 65536
#define KK 9
#define NSEG 1024               // T*F floats per (b,c) tile
#define NTOT (BB*FF*CC*TT)      // 16777216

// ---------------- scratch (device globals; no allocs allowed) ----------------
__device__ float g_deg[CC];
__device__ float g_dis[CC];
__device__ int   g_cnt[CC];
__device__ int   g_off[CC + 1];
__device__ int   g_pos[CC];
__device__ int   g_eid[EE];
__device__ float g_norm[EE];
__device__ float g_buf0[NTOT];   // x_lin  -> later reused as z (post IN1+ReLU)
__device__ float g_buf1[NTOT];   // h1 (gcn pre-norm) -> later reused as y (conv out)
__device__ float g_s1[BB*FF], g_q1[BB*FF], g_s2[BB*FF], g_q2[BB*FF];
__device__ float g_mu1[BB*FF], g_rs1[BB*FF], g_mu2[BB*FF], g_rs2[BB*FF];

// ---------------- 1: init ----------------
__global__ void k_prep() {
    int i = blockIdx.x * blockDim.x + threadIdx.x;
    if (i < CC) { g_deg[i] = 1.0f; g_cnt[i] = 0; }
    if (i < BB*FF) { g_s1[i] = 0.f; g_q1[i] = 0.f; g_s2[i] = 0.f; g_q2[i] = 0.f; }
}

// ---------------- 2: degree + bucket counts ----------------
__global__ void k_edge1(const int* __restrict__ ei, const float* __restrict__ ew) {
    int e = blockIdx.x * blockDim.x + threadIdx.x;
    if (e < EE) {
        int d = ei[EE + e];
        atomicAdd(&g_deg[d], ew[e]);
        atomicAdd(&g_cnt[d], 1);
    }
}

// ---------------- 3: prefix scan (CSR offsets) + dis ----------------
__global__ void k_scan() {
    __shared__ int s[1024];
    int tid = threadIdx.x;
    int c0 = tid * 4;
    int l0 = g_cnt[c0], l1 = g_cnt[c0+1], l2 = g_cnt[c0+2], l3 = g_cnt[c0+3];
    int tot = l0 + l1 + l2 + l3;
    s[tid] = tot;
    __syncthreads();
    for (int d = 1; d < 1024; d <<= 1) {
        int v = 0;
        if (tid >= d) v = s[tid - d];
        __syncthreads();
        if (tid >= d) s[tid] += v;
        __syncthreads();
    }
    int excl = s[tid] - tot;
    g_off[c0]   = excl;              g_pos[c0]   = excl;
    g_off[c0+1] = excl + l0;         g_pos[c0+1] = excl + l0;
    g_off[c0+2] = excl + l0 + l1;    g_pos[c0+2] = excl + l0 + l1;
    g_off[c0+3] = excl + l0 + l1 + l2; g_pos[c0+3] = excl + l0 + l1 + l2;
    if (tid == 1023) g_off[CC] = s[1023];
    g_dis[c0]   = rsqrtf(g_deg[c0]);
    g_dis[c0+1] = rsqrtf(g_deg[c0+1]);
    g_dis[c0+2] = rsqrtf(g_deg[c0+2]);
    g_dis[c0+3] = rsqrtf(g_deg[c0+3]);
}

// ---------------- 4: fill CSR + edge norms ----------------
__global__ void k_edge2(const int* __restrict__ ei, const float* __restrict__ ew) {
    int e = blockIdx.x * blockDim.x + threadIdx.x;
    if (e < EE) {
        int sN = ei[e];
        int d  = ei[EE + e];
        int slot = atomicAdd(&g_pos[d], 1);
        g_eid[slot] = e;
        g_norm[e] = g_dis[sN] * ew[e] * g_dis[d];
    }
}

// ---------------- 5: x_lin[b,c,t,g] = sum_f x[b,f,c,t] * W[f,g] ----------------
__global__ void k_xlin(const float* __restrict__ x, const float* __restrict__ W) {
    __shared__ float xs[32 * 33];
    __shared__ float ws[1024];
    int tid = threadIdx.x;
    int bc = blockIdx.x;
    int b = bc >> 12, c = bc & (CC - 1);
    int lf = tid >> 5, lt = tid & 31;
    xs[lt * 33 + lf] = x[(((size_t)b * FF + lf) * CC + c) * TT + lt];
    ws[tid] = W[tid];
    __syncthreads();
    int g = tid & 31, t = tid >> 5;
    float wreg[32];
#pragma unroll
    for (int f = 0; f < 32; ++f) wreg[f] = ws[f * 32 + g];
    float acc = 0.f;
#pragma unroll
    for (int f = 0; f < 32; ++f) acc += xs[t * 33 + f] * wreg[f];
    g_buf0[((size_t)b * CC + c) * NSEG + tid] = acc;
}

// ---------------- 6: aggregate (gather form) + bias + stats1 ----------------
__global__ void k_agg(const int* __restrict__ ei, const float* __restrict__ gcnb) {
    __shared__ int   s_src[256];
    __shared__ float s_nrm[256];
    __shared__ float sred[1024];
    int tid = threadIdx.x;
    int bc = blockIdx.x;
    int b = bc >> 12, c = bc & (CC - 1);
    size_t base = ((size_t)b * CC + c) * NSEG;
    float ds = g_dis[c];
    float acc = g_buf0[base + tid] * (ds * ds);        // self-loop term
    int beg = g_off[c], end = g_off[c + 1];
    for (int j0 = beg; j0 < end; j0 += 256) {
        int n = min(256, end - j0);
        __syncthreads();
        if (tid < n) {
            int e = g_eid[j0 + tid];
            s_src[tid] = ei[e];
            s_nrm[tid] = g_norm[e];
        }
        __syncthreads();
        int j = 0;
        for (; j + 4 <= n; j += 4) {
            float v0 = g_buf0[((size_t)b * CC + s_src[j    ]) * NSEG + tid];
            float v1 = g_buf0[((size_t)b * CC + s_src[j + 1]) * NSEG + tid];
            float v2 = g_buf0[((size_t)b * CC + s_src[j + 2]) * NSEG + tid];
            float v3 = g_buf0[((size_t)b * CC + s_src[j + 3]) * NSEG + tid];
            acc += v0 * s_nrm[j];
            acc += v1 * s_nrm[j + 1];
            acc += v2 * s_nrm[j + 2];
            acc += v3 * s_nrm[j + 3];
        }
        for (; j < n; ++j)
            acc += g_buf0[((size_t)b * CC + s_src[j]) * NSEG + tid] * s_nrm[j];
    }
    int g = tid & 31;
    acc += gcnb[g];
    g_buf1[base + tid] = acc;
    // per-(b,g) partial stats
    __syncthreads();
    sred[tid] = acc;
    __syncthreads();
#pragma unroll
    for (int st = 512; st >= 32; st >>= 1) {
        if (tid < st) sred[tid] += sred[tid + st];
        __syncthreads();
    }
    if (tid < 32) atomicAdd(&g_s1[b * 32 + tid], sred[tid]);
    __syncthreads();
    sred[tid] = acc * acc;
    __syncthreads();
#pragma unroll
    for (int st = 512; st >= 32; st >>= 1) {
        if (tid < st) sred[tid] += sred[tid + st];
        __syncthreads();
    }
    if (tid < 32) atomicAdd(&g_q1[b * 32 + tid], sred[tid]);
}

// ---------------- 7/10: finalize stats ----------------
__global__ void k_fin(int stage) {
    int i = threadIdx.x;
    if (i < BB * FF) {
        const float invN = 1.0f / (float)(CC * TT);
        float s = stage ? g_s2[i] : g_s1[i];
        float q = stage ? g_q2[i] : g_q1[i];
        float m = s * invN;
        float v = q * invN - m * m;
        float r = rsqrtf(v + 1e-5f);
        if (stage) { g_mu2[i] = m; g_rs2[i] = r; }
        else       { g_mu1[i] = m; g_rs1[i] = r; }
    }
}

// ---------------- 8: IN1 + ReLU (h1 -> z) ----------------
__global__ void k_in1() {
    int i4 = blockIdx.x * blockDim.x + threadIdx.x;   // NTOT/4 total
    float4 v = ((const float4*)g_buf1)[i4];
    int b = i4 >> 20;                                  // 2^20 float4 per batch
    int gq = i4 & 7;                                   // g/4
    float4 mu = ((const float4*)g_mu1)[b * 8 + gq];
    float4 rs = ((const float4*)g_rs1)[b * 8 + gq];
    float4 o;
    o.x = fmaxf(0.f, (v.x - mu.x) * rs.x);
    o.y = fmaxf(0.f, (v.y - mu.y) * rs.y);
    o.z = fmaxf(0.f, (v.z - mu.z) * rs.z);
    o.w = fmaxf(0.f, (v.w - mu.w) * rs.w);
    ((float4*)g_buf0)[i4] = o;
}

// ---------------- 9: temporal conv (1xK) + bias + stats2 ----------------
// block = 256 threads = 2 (b,c) tiles; thread computes 4 t x 2 o outputs.
__global__ void k_conv(const float* __restrict__ cw, const float* __restrict__ cb) {
    __shared__ float ws[KK * 1024];      // [k][i][o]
    __shared__ float zt[2][1280];        // [tile][(t+4)*32 + i], zero halo
    int tid = threadIdx.x;
    int bc2 = blockIdx.x;                // BB*CC/2
    int b = bc2 >> 11;
    int cpair = bc2 & 2047;
    int tile = tid >> 7;
    int r = tid & 127;
    int c = cpair * 2 + tile;
    for (int idx = tid; idx < KK * 1024; idx += 256) {
        int k = idx >> 10;
        int rem = idx & 1023;
        int i = rem >> 5, o = rem & 31;
        ws[idx] = cw[(o * 32 + i) * KK + k];
    }
    size_t base = ((size_t)b * CC + c) * NSEG;
    for (int idx = r; idx < 1280; idx += 128) {
        int row = idx >> 5;
        float v = 0.f;
        if (row >= 4 && row < 36) v = g_buf0[base + (row - 4) * 32 + (idx & 31)];
        zt[tile][idx] = v;
    }
    __syncthreads();
    int o0 = (r & 15) * 2;
    int tb = (r >> 4) * 4;
    float bias0 = cb[o0], bias1 = cb[o0 + 1];
    float a00 = bias0, a01 = bias1, a10 = bias0, a11 = bias1;
    float a20 = bias0, a21 = bias1, a30 = bias0, a31 = bias1;
    const float* ztt = zt[tile];
#pragma unroll 1
    for (int k = 0; k < KK; ++k) {
        const float* wk = ws + k * 1024 + o0;
        const float* zr = ztt + (tb + k) * 32;
#pragma unroll
        for (int i = 0; i < 32; ++i) {
            float w0 = wk[i * 32], w1 = wk[i * 32 + 1];
            float z0 = zr[i], z1 = zr[32 + i], z2 = zr[64 + i], z3 = zr[96 + i];
            a00 += z0 * w0; a01 += z0 * w1;
            a10 += z1 * w0; a11 += z1 * w1;
            a20 += z2 * w0; a21 += z2 * w1;
            a30 += z3 * w0; a31 += z3 * w1;
        }
    }
    size_t yb = base + (size_t)tb * 32 + o0;
    *(float2*)&g_buf1[yb]      = make_float2(a00, a01);
    *(float2*)&g_buf1[yb + 32] = make_float2(a10, a11);
    *(float2*)&g_buf1[yb + 64] = make_float2(a20, a21);
    *(float2*)&g_buf1[yb + 96] = make_float2(a30, a31);
    // stats2: per-o partial sums, reduce over threads sharing (tid & 15)
    float p0 = a00 + a10 + a20 + a30;
    float p1 = a01 + a11 + a21 + a31;
    float q0 = a00*a00 + a10*a10 + a20*a20 + a30*a30;
    float q1 = a01*a01 + a11*a11 + a21*a21 + a31*a31;
    float* red = &zt[0][0];
    __syncthreads();
    red[tid] = p0; __syncthreads();
#pragma unroll
    for (int st = 128; st >= 16; st >>= 1) { if (tid < st) red[tid] += red[tid + st]; __syncthreads(); }
    if (tid < 16) atomicAdd(&g_s2[b * 32 + tid * 2], red[tid]);
    __syncthreads();
    red[tid] = p1; __syncthreads();
#pragma unroll
    for (int st = 128; st >= 16; st >>= 1) { if (tid < st) red[tid] += red[tid + st]; __syncthreads(); }
    if (tid < 16) atomicAdd(&g_s2[b * 32 + tid * 2 + 1], red[tid]);
    __syncthreads();
    red[tid] = q0; __syncthreads();
#pragma unroll
    for (int st = 128; st >= 16; st >>= 1) { if (tid < st) red[tid] += red[tid + st]; __syncthreads(); }
    if (tid < 16) atomicAdd(&g_q2[b * 32 + tid * 2], red[tid]);
    __syncthreads();
    red[tid] = q1; __syncthreads();
#pragma unroll
    for (int st = 128; st >= 16; st >>= 1) { if (tid < st) red[tid] += red[tid + st]; __syncthreads(); }
    if (tid < 16) atomicAdd(&g_q2[b * 32 + tid * 2 + 1], red[tid]);
}

// ---------------- 11: IN2 + ReLU + residual + ReLU + transpose ----------------
__global__ void k_final(const float* __restrict__ x, float* __restrict__ out) {
    __shared__ float sy[32 * 33];
    int tid = threadIdx.x;
    int bc = blockIdx.x;
    int b = bc >> 12, c = bc & (CC - 1);
    size_t base = ((size_t)b * CC + c) * NSEG;
    int o = tid & 31, t = tid >> 5;
    float v = g_buf1[base + tid];
    v = fmaxf(0.f, (v - g_mu2[b * 32 + o]) * g_rs2[b * 32 + o]);
    sy[t * 33 + o] = v;
    __syncthreads();
    int f = tid >> 5, t2 = tid & 31;
    size_t xi = (((size_t)b * FF + f) * CC + c) * TT + t2;
    out[xi] = fmaxf(0.f, sy[t2 * 33 + f] + x[xi]);
}

// ---------------- launch ----------------
extern "C" void kernel_launch(void* const* d_in, const int* in_sizes, int n_in,
                              void* d_out, int out_size) {
    const float* x    = (const float*)d_in[0];
    const int*   ei   = (const int*)d_in[1];
    const float* ew   = (const float*)d_in[2];
    const float* W    = (const float*)d_in[3];
    const float* gcnb = (const float*)d_in[4];
    const float* cw   = (const float*)d_in[5];
    const float* cb   = (const float*)d_in[6];
    float* out = (float*)d_out;

    k_prep <<<16, 256>>>();
    k_edge1<<<EE / 256, 256>>>(ei, ew);
    k_scan <<<1, 1024>>>();
    k_edge2<<<EE / 256, 256>>>(ei, ew);
    k_xlin <<<BB * CC, 1024>>>(x, W);
    k_agg  <<<BB * CC, 1024>>>(ei, gcnb);
    k_fin  <<<1, 128>>>(0);
    k_in1  <<<NTOT / 4 / 256, 256>>>();
    k_conv <<<BB * CC / 2, 256>>>(cw, cb);
    k_fin  <<<1, 128>>>(1);
    k_final<<<BB * CC, 1024>>>(x, out);
}